// round 5
// baseline (speedup 1.0000x reference)
#include <cuda_runtime.h>

// GATLayer: B=8, N=1024, INP=7, D=32, H=4
// Identity: softmax_j(s_i + s_j + ba) == softmax_j(s_j) (s_i, ba constant in j)
// => attention weights independent of i => output row constant per batch.

#define BB 8
#define NN 1024
#define DD 32
#define HH 4

__device__ float4 g_fx4[BB * NN * 8];        // fx [8192][32] as float4[8192][8]
__device__ float4 g_s4[BB * NN];             // s_j [8192][4]
__device__ __align__(16) float g_o[BB * DD]; // per-batch output row [8][32]

static __device__ __forceinline__ float lrelu(float t) {
    return fmaxf(t, 0.2f * t);
}

// ---------------------------------------------------------------------------
// Kernel 1: message MLP + s_j.
// 256 blocks x 256 threads; 8 threads per node (lane-group s = t&7).
//  L1: k-split   — lane s computes h1 units [8s, 8s+8)   (no duplication)
//  L2: j-split   — lane s computes a units  [8s, 8s+8), h1 via shfl exchange
//  L3: d-split   — lane s computes fx dims  [4s, 4s+4),  h2 via shfl exchange
// All cross-lane traffic is __shfl_sync inside the 8-lane node group.
// W1/W2 float4 reads use a per-half rotation so the 8 lanes hit distinct banks.
// ---------------------------------------------------------------------------
__global__ __launch_bounds__(256) void k_mlp(
    const float* __restrict__ x,
    const float* __restrict__ W1, const float* __restrict__ b1,
    const float* __restrict__ W2, const float* __restrict__ b2,
    const float* __restrict__ W3, const float* __restrict__ b3,
    const float* __restrict__ Wa)
{
    __shared__ float sW1[7 * 64];
    __shared__ float sW2[64 * 64];
    __shared__ float sW3[64 * 32];
    __shared__ float sWaj[32 * 4];     // Wa rows 32..63, [d][h]
    __shared__ float sb1[64], sb2[64], sb3[32];

    const int t = threadIdx.x;

    // ---- stage weights (float4) ----
    {
        float4* d2 = (float4*)sW2; const float4* s2 = (const float4*)W2;
#pragma unroll
        for (int i = 0; i < 4; i++) d2[t + i * 256] = s2[t + i * 256];
        float4* d3 = (float4*)sW3; const float4* s3 = (const float4*)W3;
#pragma unroll
        for (int i = 0; i < 2; i++) d3[t + i * 256] = s3[t + i * 256];
        if (t < 112) ((float4*)sW1)[t] = ((const float4*)W1)[t];
        else if (t < 144) ((float4*)sWaj)[t - 112] = ((const float4*)(Wa + 128))[t - 112];
        else if (t < 160) ((float4*)sb1)[t - 144] = ((const float4*)b1)[t - 144];
        else if (t < 176) ((float4*)sb2)[t - 160] = ((const float4*)b2)[t - 160];
        else if (t < 184) ((float4*)sb3)[t - 176] = ((const float4*)b3)[t - 176];
    }
    __syncthreads();

    const int node = blockIdx.x * 32 + (t >> 3);
    const int s = t & 7;
    const int gbase = (t & 31) & 24;   // 8-lane group base within warp
    const int rot = s >> 2;            // 0 or 1: swap float4 read order

    float xv[7];
    const float* xp = x + node * 7;
#pragma unroll
    for (int k = 0; k < 7; k++) xv[k] = __ldg(xp + k);

    // ---- layer 1: h1[8] = lrelu(b1 + x @ W1) for units [8s, 8s+8) ----
    float h1[8];
#pragma unroll
    for (int c = 0; c < 2; c++) {
        const int cc = (c + rot) & 1;
        const float4 b = ((const float4*)sb1)[2 * s + cc];
        h1[cc * 4 + 0] = b.x; h1[cc * 4 + 1] = b.y;
        h1[cc * 4 + 2] = b.z; h1[cc * 4 + 3] = b.w;
    }
#pragma unroll
    for (int k = 0; k < 7; k++) {
        const float xk = xv[k];
        const float4* row = (const float4*)(sW1 + k * 64);
#pragma unroll
        for (int c = 0; c < 2; c++) {
            const int cc = (c + rot) & 1;
            const float4 w = row[2 * s + cc];
            h1[cc * 4 + 0] += xk * w.x;
            h1[cc * 4 + 1] += xk * w.y;
            h1[cc * 4 + 2] += xk * w.z;
            h1[cc * 4 + 3] += xk * w.w;
        }
    }
#pragma unroll
    for (int i = 0; i < 8; i++) h1[i] = lrelu(h1[i]);

    // ---- layer 2: a8[8] for units [8s, 8s+8); h1[k] fetched from owner lane
    float a8[8];
#pragma unroll
    for (int c = 0; c < 2; c++) {
        const int cc = (c + rot) & 1;
        const float4 b = ((const float4*)sb2)[2 * s + cc];
        a8[cc * 4 + 0] = b.x; a8[cc * 4 + 1] = b.y;
        a8[cc * 4 + 2] = b.z; a8[cc * 4 + 3] = b.w;
    }
#pragma unroll
    for (int k = 0; k < 64; k++) {
        const float hk = __shfl_sync(0xffffffffu, h1[k & 7], gbase + (k >> 3));
        const float4* row = (const float4*)(sW2 + k * 64);
#pragma unroll
        for (int c = 0; c < 2; c++) {
            const int cc = (c + rot) & 1;
            const float4 w = row[2 * s + cc];
            a8[cc * 4 + 0] += hk * w.x;
            a8[cc * 4 + 1] += hk * w.y;
            a8[cc * 4 + 2] += hk * w.z;
            a8[cc * 4 + 3] += hk * w.w;
        }
    }
    float h2[8];
#pragma unroll
    for (int i = 0; i < 8; i++) h2[i] = lrelu(a8[i]);

    // ---- layer 3: fx dims [4s, 4s+4); h2[j] fetched from owner lane.
    // Two accumulator sets (even/odd j) to halve the FFMA chain depth.
    const float4 b3v = ((const float4*)sb3)[s];
    float e0 = b3v.x, e1 = b3v.y, e2 = b3v.z, e3 = b3v.w;
    float o0 = 0.f, o1 = 0.f, o2 = 0.f, o3 = 0.f;
#pragma unroll
    for (int j = 0; j < 64; j += 2) {
        const float hj0 = __shfl_sync(0xffffffffu, h2[j & 7], gbase + (j >> 3));
        const float hj1 = __shfl_sync(0xffffffffu, h2[(j + 1) & 7], gbase + ((j + 1) >> 3));
        const float4 w0 = ((const float4*)sW3)[j * 8 + s];
        const float4 w1 = ((const float4*)sW3)[(j + 1) * 8 + s];
        e0 += hj0 * w0.x; e1 += hj0 * w0.y; e2 += hj0 * w0.z; e3 += hj0 * w0.w;
        o0 += hj1 * w1.x; o1 += hj1 * w1.y; o2 += hj1 * w1.z; o3 += hj1 * w1.w;
    }
    const float f0 = e0 + o0, f1 = e1 + o1, f2 = e2 + o2, f3 = e3 + o3;

    // each lane owns one float4 of fx -> direct store
    g_fx4[node * 8 + s] = make_float4(f0, f1, f2, f3);

    // ---- s_j = fx @ Wa[D:] : partial over this lane's 4 dims, 8-lane reduce
    float sj0 = 0.f, sj1 = 0.f, sj2 = 0.f, sj3 = 0.f;
    {
        const float4 w0 = ((const float4*)sWaj)[4 * s + 0];
        const float4 w1 = ((const float4*)sWaj)[4 * s + 1];
        const float4 w2 = ((const float4*)sWaj)[4 * s + 2];
        const float4 w3 = ((const float4*)sWaj)[4 * s + 3];
        sj0 = f0 * w0.x + f1 * w1.x + f2 * w2.x + f3 * w3.x;
        sj1 = f0 * w0.y + f1 * w1.y + f2 * w2.y + f3 * w3.y;
        sj2 = f0 * w0.z + f1 * w1.z + f2 * w2.z + f3 * w3.z;
        sj3 = f0 * w0.w + f1 * w1.w + f2 * w2.w + f3 * w3.w;
    }
#pragma unroll
    for (int o = 1; o < 8; o <<= 1) {
        sj0 += __shfl_xor_sync(0xffffffffu, sj0, o);
        sj1 += __shfl_xor_sync(0xffffffffu, sj1, o);
        sj2 += __shfl_xor_sync(0xffffffffu, sj2, o);
        sj3 += __shfl_xor_sync(0xffffffffu, sj3, o);
    }
    if (s == 0) g_s4[node] = make_float4(sj0, sj1, sj2, sj3);
}

// ---------------------------------------------------------------------------
// Kernel 2: per-batch softmax over j, aggregation m[h][d] (fx tiled through
// shared), projection. 8 blocks x 256 threads.
// ---------------------------------------------------------------------------
__global__ __launch_bounds__(256) void k_att(
    const float* __restrict__ Ws, const float* __restrict__ bs)
{
    const int b = blockIdx.x;
    const int t = threadIdx.x;
    const int w = t >> 5, lane = t & 31;

    __shared__ float ps[4 * 1024];   // exp(s - max), [h][j]
    __shared__ float4 sfx4[256 * 8]; // 256-row fx tile (32 KB)
    __shared__ float red[4 * 8];
    __shared__ float part[256];
    __shared__ float sm[128];
    __shared__ float pr2[128];

    // ---- load s, per-head max ----
    float sv[4][4];
    float lmax[4] = { -1e30f, -1e30f, -1e30f, -1e30f };
#pragma unroll
    for (int jj = 0; jj < 4; jj++) {
        const float4 v = g_s4[b * 1024 + jj * 256 + t];
        sv[jj][0] = v.x; sv[jj][1] = v.y; sv[jj][2] = v.z; sv[jj][3] = v.w;
        lmax[0] = fmaxf(lmax[0], v.x); lmax[1] = fmaxf(lmax[1], v.y);
        lmax[2] = fmaxf(lmax[2], v.z); lmax[3] = fmaxf(lmax[3], v.w);
    }
#pragma unroll
    for (int o = 16; o > 0; o >>= 1)
#pragma unroll
        for (int h = 0; h < 4; h++)
            lmax[h] = fmaxf(lmax[h], __shfl_xor_sync(0xffffffffu, lmax[h], o));
    if (lane == 0)
#pragma unroll
        for (int h = 0; h < 4; h++) red[h * 8 + w] = lmax[h];
    __syncthreads();
    float mx[4];
#pragma unroll
    for (int h = 0; h < 4; h++) {
        float m = red[h * 8];
#pragma unroll
        for (int ww = 1; ww < 8; ww++) m = fmaxf(m, red[h * 8 + ww]);
        mx[h] = m;
    }
    __syncthreads();

    // ---- exp + per-head sum ----
    float lsum[4] = { 0.f, 0.f, 0.f, 0.f };
#pragma unroll
    for (int jj = 0; jj < 4; jj++) {
        const int j = jj * 256 + t;
#pragma unroll
        for (int h = 0; h < 4; h++) {
            const float e = __expf(sv[jj][h] - mx[h]);
            ps[h * 1024 + j] = e;
            lsum[h] += e;
        }
    }
#pragma unroll
    for (int o = 16; o > 0; o >>= 1)
#pragma unroll
        for (int h = 0; h < 4; h++)
            lsum[h] += __shfl_xor_sync(0xffffffffu, lsum[h], o);
    if (lane == 0)
#pragma unroll
        for (int h = 0; h < 4; h++) red[h * 8 + w] = lsum[h];
    __syncthreads();
    float sums[4];
#pragma unroll
    for (int h = 0; h < 4; h++) {
        float s = red[h * 8];
#pragma unroll
        for (int ww = 1; ww < 8; ww++) s += red[h * 8 + ww];
        sums[h] = s;
    }

    // ---- aggregation: m[h][d] = sum_j p[h][j]*fx[j][d], fx tiled via smem.
    const int o = t & 127, half = t >> 7;
    const int h = o >> 5, d = o & 31;
    float a0 = 0.f, a1 = 0.f, a2 = 0.f, a3 = 0.f;
#pragma unroll 1
    for (int tile = 0; tile < 4; tile++) {
        __syncthreads();
        const float4* src = g_fx4 + (b * 1024 + tile * 256) * 8;
        for (int i = t; i < 2048; i += 256) sfx4[i] = src[i];
        __syncthreads();
        const float* pr  = ps + h * 1024 + tile * 256 + half * 128;
        const float* fxp = (const float*)sfx4 + half * 128 * 32 + d;
#pragma unroll 8
        for (int jj = 0; jj < 128; jj += 4) {
            a0 += pr[jj + 0] * fxp[(jj + 0) * 32];
            a1 += pr[jj + 1] * fxp[(jj + 1) * 32];
            a2 += pr[jj + 2] * fxp[(jj + 2) * 32];
            a3 += pr[jj + 3] * fxp[(jj + 3) * 32];
        }
    }
    part[t] = (a0 + a1) + (a2 + a3);
    __syncthreads();
    if (t < 128) sm[t] = (part[t] + part[t + 128]) / sums[h];
    __syncthreads();

    // ---- projection
    if (t < 128) {
        const int kg = t >> 5, dd = t & 31;
        float a = 0.f;
#pragma unroll
        for (int kk = 0; kk < 32; kk++) {
            const int k = kg * 32 + kk;
            a += sm[k] * Ws[k * 32 + dd];
        }
        pr2[t] = a;
    }
    __syncthreads();
    if (t < 32)
        g_o[b * 32 + t] = bs[t] + ((pr2[t] + pr2[t + 32]) + (pr2[t + 64] + pr2[t + 96]));
}

// ---------------------------------------------------------------------------
// Kernel 3: broadcast per-batch rows to the full [B,N,D] output.
// ---------------------------------------------------------------------------
__global__ __launch_bounds__(256) void k_bcast(float4* __restrict__ out)
{
    const int g = blockIdx.x * 256 + threadIdx.x; // float4 index
    const int b = g >> 13;                        // 8192 float4 per batch
    const int d4 = g & 7;
    out[g] = *(const float4*)(g_o + b * 32 + d4 * 4);
}

extern "C" void kernel_launch(void* const* d_in, const int* in_sizes, int n_in,
                              void* d_out, int out_size)
{
    const float* x  = (const float*)d_in[0];
    const float* W1 = (const float*)d_in[1];
    const float* b1 = (const float*)d_in[2];
    const float* W2 = (const float*)d_in[3];
    const float* b2 = (const float*)d_in[4];
    const float* W3 = (const float*)d_in[5];
    const float* b3 = (const float*)d_in[6];
    const float* Wa = (const float*)d_in[7];
    // d_in[8] = ba: cancels in the softmax
    const float* Ws = (const float*)d_in[9];
    const float* bs = (const float*)d_in[10];

    k_mlp<<<256, 256>>>(x, W1, b1, W2, b2, W3, b3, Wa);
    k_att<<<8, 256>>>(Ws, bs);
    k_bcast<<<256, 256>>>((float4*)d_out);
}